// round 12
// baseline (speedup 1.0000x reference)
#include <cuda_runtime.h>
#include <math.h>

#define NMAX 1024
#define SMAX 256
#define NTHREADS 128
#define L2E 1.4426950408889634f
#define TTHR 1.0e-4f
#define ECUT -22.0f       // log2(w) cutoff: w < 2.4e-7 -> negligible vs 1e-3 tol

typedef unsigned long long ull;

// ---------------------------------------------------------------------------
// Single kernel. Each block handles one 16x8 tile, fully independently:
//   1. cheap conservative cull over all N (bound on cov2d spectral radius)
//   2. rank-sort candidate (z,idx) keys
//   3. per 256-window: compute exact params straight into sorted smem slots
//   4. front-to-back composite with per-pixel + block-uniform early exit
// No producers, no global flags, no inter-block traffic at all.
// ---------------------------------------------------------------------------
__global__ void __launch_bounds__(NTHREADS) render_all_kernel(
    float* __restrict__ out,
    const float* __restrict__ mean,
    const float* __restrict__ qvec,
    const float* __restrict__ svecb,
    const float* __restrict__ sh,
    const float* __restrict__ alphab,
    const float* __restrict__ c2w,
    int H, int W, int N)
{
    __shared__ ull    ckey[NMAX];     // 8KB  unsorted candidate keys
    __shared__ ull    skey[NMAX];     // 8KB  sorted candidate keys
    __shared__ float4 f0[SMAX];       // 4KB  mx, my, A, B   (sorted window)
    __shared__ float4 f1[SMAX];       // 4KB  C, la, cr, cg
    __shared__ float  fcb[SMAX];      // 1KB  blue
    __shared__ int    s_cnt;

    int tid = threadIdx.x;

    // ---- camera rows (c2w is 16 floats, L2/L1-hot after first wave) ----
    const float4* cw4 = (const float4*)c2w;
    float4 cwa = __ldg(cw4 + 0);
    float4 cwb = __ldg(cw4 + 1);
    float4 cwc = __ldg(cw4 + 2);
    float W00 = cwa.x, W01 = cwb.x, W02 = cwc.x;   // Rw[i][j] = c2w[j][i]
    float W10 = cwa.y, W11 = cwb.y, W12 = cwc.y;
    float W20 = cwa.z, W21 = cwb.z, W22 = cwc.z;
    float t0 = cwa.w, t1 = cwb.w, t2 = cwc.w;

    // ---- tile geometry: 16 wide x 8 high ----
    int tx = tid & 15;
    int ty = tid >> 4;
    int tbx = blockIdx.x;
    int tby = blockIdx.y;
    int pxi = tbx * 16 + tx;
    int pyi = tby * 8 + ty;

    float invW = 1.f / (float)W;
    float pxc = ((float)pxi + 0.5f - 0.5f * (float)W) * invW;
    float pyc = ((float)pyi + 0.5f - 0.5f * (float)H) * invW;
    float xmin = ((float)(tbx * 16)      + 0.5f - 0.5f * (float)W) * invW;
    float xmax = ((float)(tbx * 16 + 15) + 0.5f - 0.5f * (float)W) * invW;
    float ymin = ((float)(tby * 8)       + 0.5f - 0.5f * (float)H) * invW;
    float ymax = ((float)(tby * 8 + 7)   + 0.5f - 0.5f * (float)H) * invW;

    if (tid == 0) s_cnt = 0;
    __syncthreads();

    // ---- phase 1: cheap conservative cull (mean + svec + alpha only) ----
#pragma unroll
    for (int r = 0; r < NMAX / NTHREADS; r++) {
        int i = r * NTHREADS + tid;
        if (i < N) {
            float m0 = mean[3 * i + 0], m1 = mean[3 * i + 1], m2 = mean[3 * i + 2];
            float sb0 = svecb[3 * i + 0], sb1 = svecb[3 * i + 1], sb2 = svecb[3 * i + 2];
            float ab = alphab[i];

            float d0 = m0 - t0, d1 = m1 - t1, d2 = m2 - t2;
            float px = W00 * d0 + W01 * d1 + W02 * d2;
            float py = W10 * d0 + W11 * d1 + W12 * d2;
            float pz = W20 * d0 + W21 * d1 + W22 * d2;
            float z = fmaxf(pz, 0.001f);
            float iz = __fdividef(1.f, z);
            float mx = px * iz;
            float my = py * iz;

            // la = log2(sigmoid(ab))
            float la = -__log2f(1.f + __expf(-ab));
            if (la > ECUT) {
                // smax^2 = exp(2*max(svecb))
                float smax2 = __expf(2.f * fmaxf(sb0, fmaxf(sb1, sb2)));
                // lam_max(cov2d) <= iz^2*(1+mx^2+my^2)*smax^2 + 1e-8
                float lamb = iz * iz * (1.f + mx * mx + my * my) * smax2 + 1e-8f;
                // cut2 = (la-ECUT)*lam_max*2/L2E ; 1.05 = fp-rounding margin
                float cut2b = 1.05f * (la - ECUT) * lamb * (2.f / L2E);
                float ddx = fmaxf(fmaxf(xmin - mx, mx - xmax), 0.f);
                float ddy = fmaxf(fmaxf(ymin - my, my - ymax), 0.f);
                if (ddx * ddx + ddy * ddy <= cut2b) {
                    int p = atomicAdd(&s_cnt, 1);
                    ckey[p] = ((ull)__float_as_uint(z) << 32) | (unsigned)i;
                }
            }
        }
    }
    __syncthreads();
    int nc = s_cnt;

    // ---- phase 2: rank-sort keys (unique -> permutation, stable (z,idx)) ----
    for (int k = tid; k < nc; k += NTHREADS) {
        ull mine = ckey[k];
        int r = 0;
        for (int j = 0; j < nc; j++) r += (ckey[j] < mine);
        skey[r] = mine;
    }
    __syncthreads();

    // ---- phase 3: windows of 256 -> exact params into sorted slots -> composite
    float T = 1.f, ar = 0.f, ag = 0.f, ab_ = 0.f;
    for (int cbase = 0; cbase < nc; cbase += SMAX) {
        int cn = min(SMAX, nc - cbase);

        for (int k = tid; k < cn; k += NTHREADS) {
            int n = (int)(skey[cbase + k] & 0xFFFFFFFFu);

            float m0 = mean[3 * n + 0], m1 = mean[3 * n + 1], m2 = mean[3 * n + 2];
            float4 q4 = __ldg((const float4*)qvec + n);
            float sb0 = svecb[3 * n + 0], sb1 = svecb[3 * n + 1], sb2 = svecb[3 * n + 2];
            float sh0 = sh[n * 27 + 0], sh9 = sh[n * 27 + 9], sh18 = sh[n * 27 + 18];
            float abv = alphab[n];

            float d0 = m0 - t0, d1 = m1 - t1, d2 = m2 - t2;
            float px = W00 * d0 + W01 * d1 + W02 * d2;
            float py = W10 * d0 + W11 * d1 + W12 * d2;
            float pz = W20 * d0 + W21 * d1 + W22 * d2;
            float z = fmaxf(pz, 0.001f);
            float iz = __fdividef(1.f, z);
            float mx = px * iz;
            float my = py * iz;

            float qw = q4.x, qx = q4.y, qy = q4.z, qz = q4.w;
            float qn = rsqrtf(qw * qw + qx * qx + qy * qy + qz * qz);
            qw *= qn; qx *= qn; qy *= qn; qz *= qn;
            float R00 = 1.f - 2.f * (qy * qy + qz * qz);
            float R01 = 2.f * (qx * qy - qw * qz);
            float R02 = 2.f * (qx * qz + qw * qy);
            float R10 = 2.f * (qx * qy + qw * qz);
            float R11 = 1.f - 2.f * (qx * qx + qz * qz);
            float R12 = 2.f * (qy * qz - qw * qx);
            float R20 = 2.f * (qx * qz - qw * qy);
            float R21 = 2.f * (qy * qz + qw * qx);
            float R22 = 1.f - 2.f * (qx * qx + qy * qy);

            float s0 = __expf(sb0);
            float s1 = __expf(sb1);
            float s2 = __expf(sb2);

            float M00 = R00 * s0, M01 = R01 * s1, M02 = R02 * s2;
            float M10 = R10 * s0, M11 = R11 * s1, M12 = R12 * s2;
            float M20 = R20 * s0, M21 = R21 * s1, M22 = R22 * s2;
            float v00 = M00 * M00 + M01 * M01 + M02 * M02;
            float v01 = M00 * M10 + M01 * M11 + M02 * M12;
            float v02 = M00 * M20 + M01 * M21 + M02 * M22;
            float v11 = M10 * M10 + M11 * M11 + M12 * M12;
            float v12 = M10 * M20 + M11 * M21 + M12 * M22;
            float v22 = M20 * M20 + M21 * M21 + M22 * M22;

            float u00 = W00 * v00 + W01 * v01 + W02 * v02;
            float u01 = W00 * v01 + W01 * v11 + W02 * v12;
            float u02 = W00 * v02 + W01 * v12 + W02 * v22;
            float u10 = W10 * v00 + W11 * v01 + W12 * v02;
            float u11 = W10 * v01 + W11 * v11 + W12 * v12;
            float u12 = W10 * v02 + W11 * v12 + W12 * v22;
            float u20 = W20 * v00 + W21 * v01 + W22 * v02;
            float u21 = W20 * v01 + W21 * v11 + W22 * v12;
            float u22 = W20 * v02 + W21 * v12 + W22 * v22;

            float c00 = u00 * W00 + u01 * W01 + u02 * W02;
            float c01 = u00 * W10 + u01 * W11 + u02 * W12;
            float c02 = u00 * W20 + u01 * W21 + u02 * W22;
            float c11 = u10 * W10 + u11 * W11 + u12 * W12;
            float c12 = u10 * W20 + u11 * W21 + u12 * W22;
            float c22 = u20 * W20 + u21 * W21 + u22 * W22;

            float iz2 = iz * iz;
            float j02 = -px * iz2;
            float j12 = -py * iz2;
            float r0a = iz * c00 + j02 * c02;
            float r0b = iz * c01 + j02 * c12;
            float r0c = iz * c02 + j02 * c22;
            float r1b = iz * c11 + j12 * c12;
            float r1c = iz * c12 + j12 * c22;
            float a2d = r0a * iz + r0c * j02 + 1e-8f;
            float b2d = r0b * iz + r0c * j12;
            float c2d = r1b * iz + r1c * j12 + 1e-8f;

            float idet = __fdividef(1.f, a2d * c2d - b2d * b2d);
            float ia = c2d * idet;
            float ib = -b2d * idet;
            float ic = a2d * idet;

            float A = -0.5f * L2E * ia;
            float B = -L2E * ib;
            float C = -0.5f * L2E * ic;

            float la = -__log2f(1.f + __expf(-abv));

            const float SHB = 0.28209479177387814f;
            float cr = __fdividef(1.f, 1.f + __expf(-SHB * sh0));
            float cg = __fdividef(1.f, 1.f + __expf(-SHB * sh9));
            float cb = __fdividef(1.f, 1.f + __expf(-SHB * sh18));

            f0[k]  = make_float4(mx, my, A, B);
            f1[k]  = make_float4(C, la, cr, cg);
            fcb[k] = cb;
        }
        __syncthreads();

        if (T > TTHR) {
            int Me = cn & ~1;
            int k = 0;
            for (; k < Me; k += 2) {
                float4 p0a = f0[k],     p1a = f1[k];
                float4 p0b = f0[k + 1], p1b = f1[k + 1];
                float cba = fcb[k], cbb = fcb[k + 1];
                float dxa = pxc - p0a.x, dya = pyc - p0a.y;
                float dxb = pxc - p0b.x, dyb = pyc - p0b.y;
                float ea = fmaf(p0a.z * dxa, dxa, fmaf(p0a.w * dxa, dya, p1a.x * dya * dya)) + p1a.y;
                float eb = fmaf(p0b.z * dxb, dxb, fmaf(p0b.w * dxb, dyb, p1b.x * dyb * dyb)) + p1b.y;
                float wa, wb;
                asm("ex2.approx.ftz.f32 %0, %1;" : "=f"(wa) : "f"(ea));
                asm("ex2.approx.ftz.f32 %0, %1;" : "=f"(wb) : "f"(eb));
                float wTa = wa * T;
                ar  = fmaf(wTa, p1a.z, ar);
                ag  = fmaf(wTa, p1a.w, ag);
                ab_ = fmaf(wTa, cba, ab_);
                float T1 = T * (1.f - fminf(wa, 0.9999f));
                if (T1 > TTHR) {
                    float wTb = wb * T1;
                    ar  = fmaf(wTb, p1b.z, ar);
                    ag  = fmaf(wTb, p1b.w, ag);
                    ab_ = fmaf(wTb, cbb, ab_);
                    T = T1 * (1.f - fminf(wb, 0.9999f));
                    if (T <= TTHR) break;
                } else {
                    T = T1;
                    break;
                }
            }
            if (k == Me && Me < cn && T > TTHR) {
                float4 p0a = f0[Me], p1a = f1[Me];
                float cba = fcb[Me];
                float dxa = pxc - p0a.x, dya = pyc - p0a.y;
                float ea = fmaf(p0a.z * dxa, dxa, fmaf(p0a.w * dxa, dya, p1a.x * dya * dya)) + p1a.y;
                float wa;
                asm("ex2.approx.ftz.f32 %0, %1;" : "=f"(wa) : "f"(ea));
                float wTa = wa * T;
                ar  = fmaf(wTa, p1a.z, ar);
                ag  = fmaf(wTa, p1a.w, ag);
                ab_ = fmaf(wTa, cba, ab_);
                T = T * (1.f - fminf(wa, 0.9999f));
            }
        }
        if (__syncthreads_and(T <= TTHR)) break;
    }

    if (pxi < W && pyi < H) {
        int o = (pyi * W + pxi) * 3;
        out[o + 0] = ar;
        out[o + 1] = ag;
        out[o + 2] = ab_;
    }
}

// ---------------------------------------------------------------------------
extern "C" void kernel_launch(void* const* d_in, const int* in_sizes, int n_in,
                              void* d_out, int out_size)
{
    const float* mean  = (const float*)d_in[0];
    const float* qvec  = (const float*)d_in[1];
    const float* svecb = (const float*)d_in[2];
    const float* sh    = (const float*)d_in[3];
    const float* alphb = (const float*)d_in[4];
    const float* c2w   = (const float*)d_in[5];

    int N = in_sizes[0] / 3;
    if (N > NMAX) N = NMAX;
    int HW = out_size / 3;
    int W = (int)(sqrtf((float)HW) + 0.5f);
    int H = HW / W;

    int ntx = (W + 15) / 16;
    int nty = (H + 7) / 8;

    dim3 grid(ntx, nty);
    render_all_kernel<<<grid, NTHREADS>>>((float*)d_out, mean, qvec, svecb, sh,
                                          alphb, c2w, H, W, N);
}

// round 13
// speedup vs baseline: 1.3158x; 1.3158x over previous
#include <cuda_runtime.h>
#include <math.h>

#define NMAX 1024
#define SMAX 256          // staged (prefetched) survivors; overflow -> global fallback
#define NTHREADS 128
#define NPRE 8            // producer blocks; chunk b = gaussians [128b, 128b+128)
#define L2E 1.4426950408889634f
#define TTHR 1.0e-4f
#define ECUT -22.0f

typedef unsigned long long ull;

__device__ float4   g_cull[NMAX];   // mx, my, cut2, z_bits(as float)
__device__ float4   g_p0[NMAX];     // mx, my, A, B
__device__ float4   g_p1[NMAX];     // C, la, cr, cg
__device__ float    g_cb[NMAX];     // blue
__device__ unsigned g_ready;        // bitmask: chunk b params visible
__device__ int      g_depart;       // reset bookkeeping

__device__ __forceinline__ unsigned ld_acquire(const unsigned* p) {
    unsigned v;
    asm volatile("ld.acquire.gpu.global.u32 %0, [%1];" : "=r"(v) : "l"(p) : "memory");
    return v;
}

// ---------------------------------------------------------------------------
__device__ __forceinline__ void precompute_one(
    int n,
    const float* __restrict__ mean,
    const float* __restrict__ qvec,
    const float* __restrict__ svecb,
    const float* __restrict__ sh,
    const float* __restrict__ alphab,
    const float* __restrict__ c2w)
{
    const float4* cw4 = (const float4*)c2w;
    float4 cwa = __ldg(cw4 + 0);
    float4 cwb = __ldg(cw4 + 1);
    float4 cwc = __ldg(cw4 + 2);
    float m0 = mean[3 * n + 0], m1 = mean[3 * n + 1], m2 = mean[3 * n + 2];
    float4 q4 = __ldg((const float4*)(qvec) + n);
    float sb0 = svecb[3 * n + 0], sb1 = svecb[3 * n + 1], sb2 = svecb[3 * n + 2];
    float sh0 = sh[n * 27 + 0], sh9 = sh[n * 27 + 9], sh18 = sh[n * 27 + 18];
    float abv = alphab[n];

    float d0 = m0 - cwa.w;
    float d1 = m1 - cwb.w;
    float d2 = m2 - cwc.w;
    float W00 = cwa.x, W01 = cwb.x, W02 = cwc.x;
    float W10 = cwa.y, W11 = cwb.y, W12 = cwc.y;
    float W20 = cwa.z, W21 = cwb.z, W22 = cwc.z;

    float px = W00 * d0 + W01 * d1 + W02 * d2;
    float py = W10 * d0 + W11 * d1 + W12 * d2;
    float pz = W20 * d0 + W21 * d1 + W22 * d2;

    float z = fmaxf(pz, 0.001f);
    float iz = __fdividef(1.f, z);
    float mx = px * iz;
    float my = py * iz;

    float qw = q4.x, qx = q4.y, qy = q4.z, qz = q4.w;
    float qn = rsqrtf(qw * qw + qx * qx + qy * qy + qz * qz);
    qw *= qn; qx *= qn; qy *= qn; qz *= qn;
    float R00 = 1.f - 2.f * (qy * qy + qz * qz);
    float R01 = 2.f * (qx * qy - qw * qz);
    float R02 = 2.f * (qx * qz + qw * qy);
    float R10 = 2.f * (qx * qy + qw * qz);
    float R11 = 1.f - 2.f * (qx * qx + qz * qz);
    float R12 = 2.f * (qy * qz - qw * qx);
    float R20 = 2.f * (qx * qz - qw * qy);
    float R21 = 2.f * (qy * qz + qw * qx);
    float R22 = 1.f - 2.f * (qx * qx + qy * qy);

    float s0 = __expf(sb0);
    float s1 = __expf(sb1);
    float s2 = __expf(sb2);

    float M00 = R00 * s0, M01 = R01 * s1, M02 = R02 * s2;
    float M10 = R10 * s0, M11 = R11 * s1, M12 = R12 * s2;
    float M20 = R20 * s0, M21 = R21 * s1, M22 = R22 * s2;
    float v00 = M00 * M00 + M01 * M01 + M02 * M02;
    float v01 = M00 * M10 + M01 * M11 + M02 * M12;
    float v02 = M00 * M20 + M01 * M21 + M02 * M22;
    float v11 = M10 * M10 + M11 * M11 + M12 * M12;
    float v12 = M10 * M20 + M11 * M21 + M12 * M22;
    float v22 = M20 * M20 + M21 * M21 + M22 * M22;

    float t00 = W00 * v00 + W01 * v01 + W02 * v02;
    float t01 = W00 * v01 + W01 * v11 + W02 * v12;
    float t02 = W00 * v02 + W01 * v12 + W02 * v22;
    float t10 = W10 * v00 + W11 * v01 + W12 * v02;
    float t11 = W10 * v01 + W11 * v11 + W12 * v12;
    float t12 = W10 * v02 + W11 * v12 + W12 * v22;
    float t20 = W20 * v00 + W21 * v01 + W22 * v02;
    float t21 = W20 * v01 + W21 * v11 + W22 * v12;
    float t22 = W20 * v02 + W21 * v12 + W22 * v22;

    float c00 = t00 * W00 + t01 * W01 + t02 * W02;
    float c01 = t00 * W10 + t01 * W11 + t02 * W12;
    float c02 = t00 * W20 + t01 * W21 + t02 * W22;
    float c11 = t10 * W10 + t11 * W11 + t12 * W12;
    float c12 = t10 * W20 + t11 * W21 + t12 * W22;
    float c22 = t20 * W20 + t21 * W21 + t22 * W22;

    float iz2 = iz * iz;
    float j02 = -px * iz2;
    float j12 = -py * iz2;
    float r0a = iz * c00 + j02 * c02;
    float r0b = iz * c01 + j02 * c12;
    float r0c = iz * c02 + j02 * c22;
    float r1b = iz * c11 + j12 * c12;
    float r1c = iz * c12 + j12 * c22;
    float a2d = r0a * iz + r0c * j02 + 1e-8f;
    float b2d = r0b * iz + r0c * j12;
    float c2d = r1b * iz + r1c * j12 + 1e-8f;

    float idet = __fdividef(1.f, a2d * c2d - b2d * b2d);
    float ia = c2d * idet;
    float ib = -b2d * idet;
    float ic = a2d * idet;

    float A = -0.5f * L2E * ia;
    float B = -L2E * ib;
    float C = -0.5f * L2E * ic;

    float alpha = __fdividef(1.f, 1.f + __expf(-abv));
    float la = __log2f(alpha);

    float mid = 0.5f * (ia + ic);
    float dif = 0.5f * (ia - ic);
    float disc = sqrtf(fmaxf(dif * dif + ib * ib, 0.f));
    float lam = mid - disc;
    float cut2 = (la <= ECUT) ? -1.f
                              : __fdividef(la - ECUT, 0.5f * L2E * fmaxf(lam, 1e-30f));

    const float SHB = 0.28209479177387814f;
    float cr = __fdividef(1.f, 1.f + __expf(-SHB * sh0));
    float cg = __fdividef(1.f, 1.f + __expf(-SHB * sh9));
    float cb = __fdividef(1.f, 1.f + __expf(-SHB * sh18));

    g_cull[n] = make_float4(mx, my, cut2, __uint_as_float(__float_as_uint(z)));
    g_p0[n]   = make_float4(mx, my, A, B);
    g_p1[n]   = make_float4(C, la, cr, cg);
    g_cb[n]   = cb;
}

// ---------------------------------------------------------------------------
// Fused kernel, chunk-pipelined producers + prefetch-at-cull consumers.
// Cull prefetches survivor params into smem staging (unsorted slots); rank
// sort emits only a permutation; composite reads staging via perm[] with a
// per-pixel early break and zero barriers.
// ---------------------------------------------------------------------------
__global__ void __launch_bounds__(NTHREADS) fused_kernel(
    float* __restrict__ out,
    const float* __restrict__ mean,
    const float* __restrict__ qvec,
    const float* __restrict__ svecb,
    const float* __restrict__ sh,
    const float* __restrict__ alphab,
    const float* __restrict__ c2w,
    int H, int W, int N)
{
    __shared__ ull    skey[NMAX];     // 8KB   survivor keys (unsorted slots)
    __shared__ float4 u0[SMAX];       // 4KB   staged params by unsorted slot
    __shared__ float4 u1[SMAX];       // 4KB
    __shared__ float  ucb[SMAX];      // 1KB
    __shared__ short  perm[NMAX];     // 2KB   sorted rank -> unsorted slot
    __shared__ int    s_cnt;

    int tid = threadIdx.x;
    int bid = blockIdx.y * gridDim.x + blockIdx.x;
    int nBlocks = gridDim.x * gridDim.y;

    // ---- tile geometry: 16 wide x 8 high ----
    int tx = tid & 15;
    int ty = tid >> 4;
    int tbx = blockIdx.x;
    int tby = blockIdx.y;
    int pxi = tbx * 16 + tx;
    int pyi = tby * 8 + ty;

    float invW = 1.f / (float)W;
    float pxc = ((float)pxi + 0.5f - 0.5f * (float)W) * invW;
    float pyc = ((float)pyi + 0.5f - 0.5f * (float)H) * invW;
    float xmin = ((float)(tbx * 16)      + 0.5f - 0.5f * (float)W) * invW;
    float xmax = ((float)(tbx * 16 + 15) + 0.5f - 0.5f * (float)W) * invW;
    float ymin = ((float)(tby * 8)       + 0.5f - 0.5f * (float)H) * invW;
    float ymax = ((float)(tby * 8 + 7)   + 0.5f - 0.5f * (float)H) * invW;

    // ---- phase 1: producers compute their chunk, publish its ready bit ----
    if (bid < NPRE) {
        int n = bid * NTHREADS + tid;
        if (n < N) precompute_one(n, mean, qvec, svecb, sh, alphab, c2w);
        __syncthreads();
        if (tid == 0) {
            __threadfence();
            atomicOr(&g_ready, 1u << bid);
        }
    }

    if (tid == 0) s_cnt = 0;
    __syncthreads();

    // ---- phase 2: cull chunk-by-chunk, prefetch params at slot grant ----
    unsigned seen = 0;
#pragma unroll
    for (int r = 0; r < NMAX / NTHREADS; r++) {
        unsigned bit = 1u << r;
        while (!(seen & bit)) seen = ld_acquire(&g_ready);
        int i = r * NTHREADS + tid;
        if (i < N) {
            float4 c = g_cull[i];
            float ddx = fmaxf(fmaxf(xmin - c.x, c.x - xmax), 0.f);
            float ddy = fmaxf(fmaxf(ymin - c.y, c.y - ymax), 0.f);
            if (ddx * ddx + ddy * ddy <= c.z) {
                int p = atomicAdd(&s_cnt, 1);
                skey[p] = ((ull)__float_as_uint(c.w) << 32) | (unsigned)i;
                if (p < SMAX) {                 // prefetch params into staging
                    u0[p]  = g_p0[i];
                    u1[p]  = g_p1[i];
                    ucb[p] = g_cb[i];
                }
            }
        }
    }
    __syncthreads();
    int total = s_cnt;

    // ---- depart + counter reset (off critical path; polls already passed) ----
    if (tid == 0) {
        int d = atomicAdd(&g_depart, 1);
        if (d == nBlocks - 1) {
            *(volatile unsigned*)&g_ready = 0;
            *(volatile int*)&g_depart = 0;
            __threadfence();
        }
    }

    // ---- phase 3: rank sort -> permutation only ----
    for (int k = tid; k < total; k += NTHREADS) {
        ull mine = skey[k];
        int r = 0;
        for (int j = 0; j < total; j++) r += (skey[j] < mine);
        perm[r] = (short)k;
    }
    __syncthreads();

    // ---- phase 4: composite, barrier-free, per-pixel early exit ----
    float T = 1.f, ar = 0.f, ag = 0.f, ab = 0.f;
    int Me = total & ~1;
    int k = 0;
    for (; k < Me; k += 2) {
        int ja = perm[k], jb = perm[k + 1];
        float4 p0a, p1a, p0b, p1b;
        float cba, cbb;
        if (ja < SMAX) { p0a = u0[ja]; p1a = u1[ja]; cba = ucb[ja]; }
        else { int idx = (int)(skey[ja] & 0xFFFFFFFFu); p0a = g_p0[idx]; p1a = g_p1[idx]; cba = g_cb[idx]; }
        if (jb < SMAX) { p0b = u0[jb]; p1b = u1[jb]; cbb = ucb[jb]; }
        else { int idx = (int)(skey[jb] & 0xFFFFFFFFu); p0b = g_p0[idx]; p1b = g_p1[idx]; cbb = g_cb[idx]; }

        float dxa = pxc - p0a.x, dya = pyc - p0a.y;
        float dxb = pxc - p0b.x, dyb = pyc - p0b.y;
        float ea = fmaf(p0a.z * dxa, dxa, fmaf(p0a.w * dxa, dya, p1a.x * dya * dya)) + p1a.y;
        float eb = fmaf(p0b.z * dxb, dxb, fmaf(p0b.w * dxb, dyb, p1b.x * dyb * dyb)) + p1b.y;
        float wa, wb;
        asm("ex2.approx.ftz.f32 %0, %1;" : "=f"(wa) : "f"(ea));
        asm("ex2.approx.ftz.f32 %0, %1;" : "=f"(wb) : "f"(eb));
        float wTa = wa * T;
        ar = fmaf(wTa, p1a.z, ar);
        ag = fmaf(wTa, p1a.w, ag);
        ab = fmaf(wTa, cba, ab);
        float T1 = T * (1.f - fminf(wa, 0.9999f));
        if (T1 > TTHR) {
            float wTb = wb * T1;
            ar = fmaf(wTb, p1b.z, ar);
            ag = fmaf(wTb, p1b.w, ag);
            ab = fmaf(wTb, cbb, ab);
            T = T1 * (1.f - fminf(wb, 0.9999f));
            if (T <= TTHR) break;
        } else {
            T = T1;
            break;
        }
    }
    if (k == Me && Me < total && T > TTHR) {   // odd tail
        int ja = perm[Me];
        float4 p0a, p1a;
        float cba;
        if (ja < SMAX) { p0a = u0[ja]; p1a = u1[ja]; cba = ucb[ja]; }
        else { int idx = (int)(skey[ja] & 0xFFFFFFFFu); p0a = g_p0[idx]; p1a = g_p1[idx]; cba = g_cb[idx]; }
        float dxa = pxc - p0a.x, dya = pyc - p0a.y;
        float ea = fmaf(p0a.z * dxa, dxa, fmaf(p0a.w * dxa, dya, p1a.x * dya * dya)) + p1a.y;
        float wa;
        asm("ex2.approx.ftz.f32 %0, %1;" : "=f"(wa) : "f"(ea));
        float wTa = wa * T;
        ar = fmaf(wTa, p1a.z, ar);
        ag = fmaf(wTa, p1a.w, ag);
        ab = fmaf(wTa, cba, ab);
    }

    if (pxi < W && pyi < H) {
        int o = (pyi * W + pxi) * 3;
        out[o + 0] = ar;
        out[o + 1] = ag;
        out[o + 2] = ab;
    }
}

// ---------------------------------------------------------------------------
extern "C" void kernel_launch(void* const* d_in, const int* in_sizes, int n_in,
                              void* d_out, int out_size)
{
    const float* mean  = (const float*)d_in[0];
    const float* qvec  = (const float*)d_in[1];
    const float* svecb = (const float*)d_in[2];
    const float* sh    = (const float*)d_in[3];
    const float* alphb = (const float*)d_in[4];
    const float* c2w   = (const float*)d_in[5];

    int N = in_sizes[0] / 3;
    if (N > NMAX) N = NMAX;
    int HW = out_size / 3;
    int W = (int)(sqrtf((float)HW) + 0.5f);
    int H = HW / W;

    int ntx = (W + 15) / 16;
    int nty = (H + 7) / 8;

    dim3 grid(ntx, nty);
    fused_kernel<<<grid, NTHREADS>>>((float*)d_out, mean, qvec, svecb, sh, alphb,
                                     c2w, H, W, N);
}